// round 13
// baseline (speedup 1.0000x reference)
#include <cuda_runtime.h>
#include <cuda_fp16.h>
#include <math.h>
#include <stdint.h>

#define DIM 512
#define NN 50000
#define NE 100000
#define TOTE (2*NE)
#define NRELS 4
#define FFDIM 1024

// ---------------- scratch (device globals; no allocation allowed) -------------
__device__ __half g_yh[NRELS*NN*DIM];    // per-rel transformed nodes (fp16)
__device__ float g_deg[NN];
__device__ float g_base[NN*DIM];
__device__ __half g_baseh[NN*DIM];
__device__ float g_agg[NN*DIM];          // scatter target / reused as FFN2 out
__device__ float g_self[NN*DIM];
__device__ float g_x1[NN*DIM];
__device__ __half g_x1h[NN*DIM];
__device__ __half g_uh[NN*FFDIM];        // FFN hidden (post-gelu) fp16
#define NWELEM 2359296
#define WREL_OFF 0
#define WSELF_OFF 1048576
#define WF1_OFF 1310720
#define WF2_OFF 1835008
__device__ __half g_wh[NWELEM];
__device__ float g_part[256*DIM];
__device__ int   g_is64;

// ---------------- index dtype detection --------------------------------------
__global__ void detect_idx_kernel(const unsigned int* __restrict__ w) {
    __shared__ int nz;
    if (threadIdx.x == 0) nz = 0;
    __syncthreads();
    int found = 0;
    for (int i = threadIdx.x; i < TOTE/2 * 2; i += blockDim.x) {
        if (w[2*i + 1] != 0u) { found = 1; break; }
        if (2*i + 1 >= TOTE - 1) break;
    }
    if (found) atomicOr(&nz, 1);
    __syncthreads();
    if (threadIdx.x == 0) g_is64 = nz ? 0 : 1;
}

__device__ __forceinline__ int ldidx(const void* p, long long i) {
    return g_is64 ? (int)((const long long*)p)[i] : ((const int*)p)[i];
}

// ---------------- edge decode --------------------------------------------------
__device__ __forceinline__ void edge_decode(const void* ei, const void* et,
                                            const float* ew, int e,
                                            int& src, int& dst, int& rel, float& w) {
    if (e < NE) {
        src = ldidx(ei, e); dst = ldidx(ei, NE + e);
        rel = ldidx(et, e); w = ew[e];
    } else {
        int e2 = e - NE;
        src = ldidx(ei, NE + e2); dst = ldidx(ei, e2);
        rel = ldidx(et, e2) + 2;  w = ew[e2];
    }
}

// ---------------- zero agg + deg ----------------------------------------------
__global__ void zero_kernel() {
    long long n4 = (long long)NN*DIM/4;
    float4* s4 = (float4*)g_agg;
    float4 z = make_float4(0.f,0.f,0.f,0.f);
    long long stride = (long long)gridDim.x * blockDim.x;
    for (long long i = (long long)blockIdx.x*blockDim.x + threadIdx.x; i < n4; i += stride)
        s4[i] = z;
    for (int i = blockIdx.x*blockDim.x + threadIdx.x; i < NN; i += (int)stride)
        g_deg[i] = 0.f;
}

// ---------------- input LayerNorm ---------------------------------------------
__global__ void input_ln_kernel(const float* __restrict__ nf, const void* __restrict__ ntype,
                                const float* __restrict__ emb, const float* __restrict__ gw,
                                const float* __restrict__ gb) {
    __shared__ float2 red[256];
    int row = blockIdx.x, t = threadIdx.x;
    int nt = ldidx(ntype, row);
    long long off = (long long)row * DIM;
    float v0 = nf[off + t]       + emb[nt*DIM + t];
    float v1 = nf[off + t + 256] + emb[nt*DIM + t + 256];
    red[t] = make_float2(v0 + v1, v0*v0 + v1*v1);
    __syncthreads();
    for (int s = 128; s > 0; s >>= 1) {
        if (t < s) { red[t].x += red[t+s].x; red[t].y += red[t+s].y; }
        __syncthreads();
    }
    float m = red[0].x * (1.f/DIM);
    float var = red[0].y * (1.f/DIM) - m*m;
    float r = rsqrtf(var + 1e-5f);
    float b0 = (v0 - m)*r*gw[t]     + gb[t];
    float b1 = (v1 - m)*r*gw[t+256] + gb[t+256];
    g_base[off + t]       = b0;
    g_base[off + t + 256] = b1;
    g_baseh[off + t]       = __float2half(b0);
    g_baseh[off + t + 256] = __float2half(b1);
}

// ---------------- edge scatter: agg[dst] += w * y[rel][src]; deg[dst] += w ----
__global__ void scatter_kernel(const void* __restrict__ ei, const void* __restrict__ et,
                               const float* __restrict__ ew) {
    int e = blockIdx.x;
    int t = threadIdx.x;   // 0..127, 4 halves each
    int src, dst, rel; float w;
    edge_decode(ei, et, ew, e, src, dst, rel, w);
    const uint2* yrow = (const uint2*)(g_yh + ((long long)rel*NN + src)*DIM);
    uint2 pk = yrow[t];
    __half2 p0 = *(__half2*)&pk.x;
    __half2 p1 = *(__half2*)&pk.y;
    float4 v;
    v.x = w * __half2float(p0.x);
    v.y = w * __half2float(p0.y);
    v.z = w * __half2float(p1.x);
    v.w = w * __half2float(p1.y);
    float* p = g_agg + (long long)dst*DIM + t*4;
    asm volatile("red.global.add.v4.f32 [%0], {%1,%2,%3,%4};"
                 :: "l"(p), "f"(v.x), "f"(v.y), "f"(v.z), "f"(v.w) : "memory");
    if (t == 0) atomicAdd(&g_deg[dst], w);
}

// ---------------- weight convert ----------------------------------------------
__global__ void conv_w_kernel(const float* __restrict__ src, int n, int off) {
    for (int i = blockIdx.x*blockDim.x + threadIdx.x; i < n; i += gridDim.x*blockDim.x)
        g_wh[off + i] = __float2half(src[i]);
}

// ================= fp16 tensor-core GEMM (NT, mma.sync) =======================
#define GBM 128
#define GBN 128
#define GBK 32

__device__ __forceinline__ void ldsm4(uint32_t* r, uint32_t addr) {
    asm volatile("ldmatrix.sync.aligned.m8n8.x4.shared.b16 {%0,%1,%2,%3},[%4];\n"
        : "=r"(r[0]), "=r"(r[1]), "=r"(r[2]), "=r"(r[3]) : "r"(addr));
}
__device__ __forceinline__ void mma_f16(float* d, const uint32_t* a, uint32_t b0, uint32_t b1) {
    asm volatile("mma.sync.aligned.m16n8k16.row.col.f32.f16.f16.f32 "
        "{%0,%1,%2,%3},{%4,%5,%6,%7},{%8,%9},{%0,%1,%2,%3};\n"
        : "+f"(d[0]), "+f"(d[1]), "+f"(d[2]), "+f"(d[3])
        : "r"(a[0]), "r"(a[1]), "r"(a[2]), "r"(a[3]), "r"(b0), "r"(b1));
}
__device__ __forceinline__ void cp16(uint32_t dst, const void* src, int sz) {
    asm volatile("cp.async.cg.shared.global [%0],[%1],16,%2;\n" :: "r"(dst), "l"(src), "r"(sz));
}

// mode: 0 = fp32 C = acc (+bias if bias)   1 = fp16 O = acc + bias
//       2 = fp16 O = gelu(acc + bias)
__global__ void __launch_bounds__(128) gemm_f16(
    const __half* __restrict__ A, const __half* __restrict__ B,
    float* __restrict__ C, __half* __restrict__ O, const float* __restrict__ bias,
    int M, int N, int K, long long bStrideZ, long long outStrideZ, long long biasStrideZ, int mode)
{
    extern __shared__ __align__(1024) char smraw[];
    const int tid = threadIdx.x;
    const int lane = tid & 31, wid = tid >> 5;
    const int wm = wid >> 1, wn = wid & 1;
    const int bm = blockIdx.y * GBM, bn = blockIdx.x * GBN, z = blockIdx.z;
    const __half* Bz = B + (long long)z * bStrideZ;
    const int niter = K / GBK;
    uint32_t smbase = (uint32_t)__cvta_generic_to_shared(smraw);

    // ---- hoisted A-row addresses (k-invariant) -------------------------------
    const int cc = tid & 3;        // 16B chunk within a 64B k-slice
    const int rr = tid >> 2;       // row-within-32-group
    long long arow[4];
    int avalid[4];
    #pragma unroll
    for (int i = 0; i < 4; i++) {
        int gr = bm + i*32 + rr;
        bool ok = (gr < M);
        arow[i] = (long long)(ok ? gr : 0) * K;
        avalid[i] = ok ? 16 : 0;
    }

    float acc[4][8][4];
    #pragma unroll
    for (int i = 0; i < 4; i++)
        #pragma unroll
        for (int j = 0; j < 8; j++)
            #pragma unroll
            for (int c = 0; c < 4; c++) acc[i][j][c] = 0.f;

    auto issue_copy = [&](int stage, int it) {
        int kb = it * GBK;
        #pragma unroll
        for (int i = 0; i < 4; i++) {
            int row = i*32 + rr;
            uint32_t dst = smbase + stage*16384
                         + (uint32_t)(row*64 + ((cc ^ ((row>>1)&3)) << 4));
            cp16(dst, A + arow[i] + kb + cc*8, avalid[i]);
        }
        #pragma unroll
        for (int i = 0; i < 4; i++) {
            int row = i*32 + rr;
            uint32_t dst = smbase + stage*16384 + 8192
                         + (uint32_t)(row*64 + ((cc ^ ((row>>1)&3)) << 4));
            cp16(dst, Bz + (long long)(bn + row)*K + kb + cc*8, 16);
        }
        asm volatile("cp.async.commit_group;\n" ::: "memory");
    };

    issue_copy(0, 0);

    for (int it = 0; it < niter; ++it) {
        if (it + 1 < niter) {
            issue_copy((it + 1) & 1, it + 1);
            asm volatile("cp.async.wait_group 1;\n" ::: "memory");
        } else {
            asm volatile("cp.async.wait_group 0;\n" ::: "memory");
        }
        __syncthreads();

        uint32_t sA = smbase + (it & 1)*16384;
        uint32_t sB = sA + 8192;
        int rsel = lane & 15;
        #pragma unroll
        for (int kk = 0; kk < 2; kk++) {
            int csel = kk*2 + (lane >> 4);
            uint32_t ah[4][4], bh[4][4];
            #pragma unroll
            for (int mi = 0; mi < 4; mi++) {
                int row = wm*64 + mi*16 + rsel;
                uint32_t off = (uint32_t)(row*64 + ((csel ^ ((row>>1)&3)) << 4));
                ldsm4(ah[mi], sA + off);
            }
            #pragma unroll
            for (int p = 0; p < 4; p++) {
                int row = wn*64 + p*16 + rsel;
                uint32_t off = (uint32_t)(row*64 + ((csel ^ ((row>>1)&3)) << 4));
                ldsm4(bh[p], sB + off);
            }
            #pragma unroll
            for (int mi = 0; mi < 4; mi++)
                #pragma unroll
                for (int nj = 0; nj < 8; nj++) {
                    int p = nj >> 1, h = nj & 1;
                    mma_f16(acc[mi][nj], ah[mi], bh[p][h], bh[p][2+h]);
                }
        }
        __syncthreads();
    }

    // ---- epilogue -----------------------------------------------------------
    #pragma unroll
    for (int mi = 0; mi < 4; mi++) {
        #pragma unroll
        for (int nj = 0; nj < 8; nj++) {
            int gc = bn + wn*64 + nj*8 + (lane & 3)*2;
            #pragma unroll
            for (int half = 0; half < 2; half++) {
                int gr = bm + wm*64 + mi*16 + (lane >> 2) + half*8;
                if (gr >= M) continue;
                float v0 = acc[mi][nj][half*2 + 0];
                float v1 = acc[mi][nj][half*2 + 1];
                if (mode == 0) {
                    if (bias) {
                        const float* bs = bias + (long long)z*biasStrideZ;
                        v0 += bs[gc]; v1 += bs[gc+1];
                    }
                    float* Cp = C + (long long)z*outStrideZ + (long long)gr*N + gc;
                    float2 w2 = make_float2(v0, v1);
                    *(float2*)Cp = w2;
                } else {
                    const float* bs = bias + (long long)z*biasStrideZ;
                    v0 += bs[gc]; v1 += bs[gc+1];
                    if (mode == 2) {
                        v0 = 0.5f * v0 * (1.f + erff(v0 * 0.70710678118654752f));
                        v1 = 0.5f * v1 * (1.f + erff(v1 * 0.70710678118654752f));
                    }
                    __half2 o;
                    o.x = __float2half(v0);
                    o.y = __float2half(v1);
                    *(__half2*)(O + (long long)z*outStrideZ + (long long)gr*N + gc) = o;
                }
            }
        }
    }
}

// ---------------- LN1: x1 = LN(base + agg/max(deg,1) + self + b_self) ---------
__global__ void ln1_kernel(const float* __restrict__ b_self, const float* __restrict__ gw,
                           const float* __restrict__ gb) {
    __shared__ float2 red[256];
    int row = blockIdx.x, t = threadIdx.x;
    long long off = (long long)row * DIM;
    float inv = 1.f / fmaxf(g_deg[row], 1.f);
    float v0 = g_base[off+t]     + g_agg[off+t]*inv     + g_self[off+t]     + b_self[t];
    float v1 = g_base[off+t+256] + g_agg[off+t+256]*inv + g_self[off+t+256] + b_self[t+256];
    red[t] = make_float2(v0 + v1, v0*v0 + v1*v1);
    __syncthreads();
    for (int s = 128; s > 0; s >>= 1) {
        if (t < s) { red[t].x += red[t+s].x; red[t].y += red[t+s].y; }
        __syncthreads();
    }
    float m = red[0].x * (1.f/DIM);
    float var = red[0].y * (1.f/DIM) - m*m;
    float r = rsqrtf(var + 1e-5f);
    float x0 = (v0 - m)*r*gw[t]     + gb[t];
    float x1 = (v1 - m)*r*gw[t+256] + gb[t+256];
    g_x1[off+t] = x0; g_x1[off+t+256] = x1;
    g_x1h[off+t]     = __float2half(x0);
    g_x1h[off+t+256] = __float2half(x1);
}

// ---------------- final fused: LN2 -> out-LN -> graph mix ---------------------
__global__ void final_fuse_kernel(const float* __restrict__ bf2,
                                  const float* __restrict__ n2g, const float* __restrict__ n2b,
                                  const float* __restrict__ og,  const float* __restrict__ ob,
                                  const float* __restrict__ gml, float* __restrict__ out) {
    __shared__ float2 red[256];
    int row = blockIdx.x, t = threadIdx.x;
    long long off = (long long)row * DIM;
    float t0 = g_x1[off+t]     + g_agg[off+t]     + bf2[t];
    float t1 = g_x1[off+t+256] + g_agg[off+t+256] + bf2[t+256];
    red[t] = make_float2(t0 + t1, t0*t0 + t1*t1);
    __syncthreads();
    for (int s = 128; s > 0; s >>= 1) {
        if (t < s) { red[t].x += red[t+s].x; red[t].y += red[t+s].y; }
        __syncthreads();
    }
    float m = red[0].x * (1.f/DIM);
    float var = red[0].y * (1.f/DIM) - m*m;
    float r = rsqrtf(var + 1e-5f);
    float x20 = (t0 - m)*r*n2g[t]     + n2b[t];
    float x21 = (t1 - m)*r*n2g[t+256] + n2b[t+256];
    __syncthreads();
    red[t] = make_float2(x20 + x21, x20*x20 + x21*x21);
    __syncthreads();
    for (int s = 128; s > 0; s >>= 1) {
        if (t < s) { red[t].x += red[t+s].x; red[t].y += red[t+s].y; }
        __syncthreads();
    }
    m = red[0].x * (1.f/DIM);
    var = red[0].y * (1.f/DIM) - m*m;
    r = rsqrtf(var + 1e-5f);
    float x30 = (x20 - m)*r*og[t]     + ob[t];
    float x31 = (x21 - m)*r*og[t+256] + ob[t+256];
    float gm = 1.f / (1.f + expf(-gml[0]));
    float b0 = g_base[off+t], b1 = g_base[off+t+256];
    out[off+t]     = b0 + gm*(x30 - b0);
    out[off+t+256] = b1 + gm*(x31 - b1);
}

// ---------------- pooling -----------------------------------------------------
__global__ void pool_part_kernel(const float* __restrict__ x) {
    int b = blockIdx.x;
    int t = threadIdx.x;
    float s = 0.f;
    for (int r = b; r < NN; r += 256)
        s += x[(long long)r*DIM + t];
    g_part[b*DIM + t] = s;
}

__global__ void pool_final_kernel(const float* __restrict__ x, const float* __restrict__ dml,
                                  float* __restrict__ pooled) {
    int t = threadIdx.x;
    float s = 0.f;
    for (int b = 0; b < 256; ++b) s += g_part[b*DIM + t];
    float mean = s * (1.f / NN);
    float dm = 1.f / (1.f + expf(-dml[0]));
    pooled[t] = dm * x[t] + (1.f - dm) * mean;
}

// ---------------- host launcher ----------------------------------------------
extern "C" void kernel_launch(void* const* d_in, const int* in_sizes, int n_in,
                              void* d_out, int out_size) {
    (void)in_sizes; (void)n_in; (void)out_size;
    const float* nf     = (const float*)d_in[0];
    const void*  ei     = d_in[1];
    const void*  et     = d_in[2];
    const void*  ntype  = d_in[3];
    const float* ew     = (const float*)d_in[4];
    const float* emb    = (const float*)d_in[5];
    const float* W_self = (const float*)d_in[6];
    const float* b_self = (const float*)d_in[7];
    const float* W_rel  = (const float*)d_in[8];
    const float* b_rel  = (const float*)d_in[9];
    const float* in_g   = (const float*)d_in[10];
    const float* in_b   = (const float*)d_in[11];
    const float* n1_g   = (const float*)d_in[12];
    const float* n1_b   = (const float*)d_in[13];
    const float* Wf1    = (const float*)d_in[14];
    const float* bf1    = (const float*)d_in[15];
    const float* Wf2    = (const float*)d_in[16];
    const float* bf2    = (const float*)d_in[17];
    const float* n2_g   = (const float*)d_in[18];
    const float* n2_b   = (const float*)d_in[19];
    const float* out_g  = (const float*)d_in[20];
    const float* out_b  = (const float*)d_in[21];
    const float* gml    = (const float*)d_in[22];
    const float* dml    = (const float*)d_in[23];
    float* out = (float*)d_out;

    static bool init = false;
    static float *p_agg, *p_self;
    static __half *p_yh, *p_bh, *p_x1h, *p_uh, *p_wh;
    static cudaStream_t s1;
    static cudaEvent_t e_begin, e_convw, e_y, e_self;
    if (!init) {
        cudaGetSymbolAddress((void**)&p_yh,   g_yh);
        cudaGetSymbolAddress((void**)&p_agg,  g_agg);
        cudaGetSymbolAddress((void**)&p_self, g_self);
        cudaGetSymbolAddress((void**)&p_bh,   g_baseh);
        cudaGetSymbolAddress((void**)&p_x1h,  g_x1h);
        cudaGetSymbolAddress((void**)&p_uh,   g_uh);
        cudaGetSymbolAddress((void**)&p_wh,   g_wh);
        cudaStreamCreateWithFlags(&s1, cudaStreamNonBlocking);
        cudaEventCreateWithFlags(&e_begin, cudaEventDisableTiming);
        cudaEventCreateWithFlags(&e_convw, cudaEventDisableTiming);
        cudaEventCreateWithFlags(&e_y,     cudaEventDisableTiming);
        cudaEventCreateWithFlags(&e_self,  cudaEventDisableTiming);
        init = true;
    }

    const int MROWS = (NN + GBM - 1) / GBM;   // 391
    const int SMEMB = 32768;

    // ---- s0: detect; fork s1 -------------------------------------------------
    detect_idx_kernel<<<1, 256>>>((const unsigned int*)ei);
    cudaEventRecord(e_begin, 0);
    cudaStreamWaitEvent(s1, e_begin, 0);

    // ---- s1: zero + weight converts (independent of inputs' LN) -------------
    zero_kernel<<<1024, 256, 0, s1>>>();
    conv_w_kernel<<<2048, 256, 0, s1>>>(W_rel,  NRELS*DIM*DIM, WREL_OFF);
    conv_w_kernel<<<512,  256, 0, s1>>>(W_self, DIM*DIM,       WSELF_OFF);
    conv_w_kernel<<<1024, 256, 0, s1>>>(Wf1,    FFDIM*DIM,     WF1_OFF);
    conv_w_kernel<<<1024, 256, 0, s1>>>(Wf2,    DIM*FFDIM,     WF2_OFF);
    cudaEventRecord(e_convw, s1);

    // ---- s0: input LN, then y GEMM (needs conv_w + zero via e_convw) ---------
    input_ln_kernel<<<NN, 256>>>(nf, ntype, emb, in_g, in_b);
    cudaStreamWaitEvent(0, e_convw, 0);
    {
        dim3 grid(DIM / GBN, MROWS, NRELS);
        gemm_f16<<<grid, 128, SMEMB>>>(p_bh, p_wh + WREL_OFF, nullptr, p_yh, b_rel,
                                       NN, DIM, DIM, (long long)DIM*DIM,
                                       (long long)NN*DIM, DIM, 1);
    }
    cudaEventRecord(e_y, 0);

    // ---- s0: scatter  ||  s1: self GEMM --------------------------------------
    scatter_kernel<<<TOTE, 128>>>(ei, et, ew);
    cudaStreamWaitEvent(s1, e_y, 0);
    {
        dim3 grid(DIM / GBN, MROWS, 1);
        gemm_f16<<<grid, 128, SMEMB, s1>>>(p_bh, p_wh + WSELF_OFF, p_self, nullptr, nullptr,
                                           NN, DIM, DIM, 0, 0, 0, 0);
    }
    cudaEventRecord(e_self, s1);
    cudaStreamWaitEvent(0, e_self, 0);

    // ---- s0: tail chain -------------------------------------------------------
    ln1_kernel<<<NN, 256>>>(b_self, n1_g, n1_b);
    {
        dim3 grid(FFDIM / GBN, MROWS, 1);
        gemm_f16<<<grid, 128, SMEMB>>>(p_x1h, p_wh + WF1_OFF, nullptr, p_uh, bf1,
                                       NN, FFDIM, DIM, 0, 0, 0, 2);
    }
    {
        dim3 grid(DIM / GBN, MROWS, 1);
        gemm_f16<<<grid, 128, SMEMB>>>(p_uh, p_wh + WF2_OFF, p_agg, nullptr, nullptr,
                                       NN, DIM, FFDIM, 0, 0, 0, 0);
    }
    final_fuse_kernel<<<NN, 256>>>(bf2, n2_g, n2_b, out_g, out_b, gml, out);
    pool_part_kernel<<<256, 512>>>(out);
    pool_final_kernel<<<1, 512>>>(out, dml, out + (long long)NN*DIM);
}

// round 15
// speedup vs baseline: 1.0898x; 1.0898x over previous
#include <cuda_runtime.h>
#include <cuda_fp16.h>
#include <math.h>
#include <stdint.h>

#define DIM 512
#define NN 50000
#define NE 100000
#define TOTE (2*NE)
#define NRELS 4
#define FFDIM 1024
#define NNP 50176              // 98*512 padded node count for scan
#define SCAN_NB 98

// ---------------- scratch (device globals; no allocation allowed) -------------
__device__ __half g_yh[NRELS*NN*DIM];    // per-rel transformed nodes (fp16)
__device__ float g_deg[NN];
__device__ float g_base[NN*DIM];
__device__ __half g_baseh[NN*DIM];
__device__ float g_agg[NN*DIM];          // FFN2 output
__device__ __half g_selfh[NN*DIM];       // base@Wself.T + b_self (fp16)
__device__ __half g_x1h[NN*DIM];
__device__ __half g_uh[NN*FFDIM];        // FFN hidden (post-gelu) fp16
#define NWELEM 2359296
#define WREL_OFF 0
#define WSELF_OFF 1048576
#define WF1_OFF 1310720
#define WF2_OFF 1835008
__device__ __half g_wh[NWELEM];
__device__ float g_part[256*DIM];
__device__ int   g_is64;
// CSR state
__device__ int   g_cnt[NNP];
__device__ int   g_cur[NNP];
__device__ int   g_off[NNP];
__device__ int   g_bsum[SCAN_NB];
__device__ int   g_boff[SCAN_NB+2];
__device__ int   g_epack[TOTE];          // src | (rel<<17)
__device__ float g_eww[TOTE];

// ---------------- index dtype detection --------------------------------------
__global__ void detect_idx_kernel(const unsigned int* __restrict__ w) {
    __shared__ int nz;
    if (threadIdx.x == 0) nz = 0;
    __syncthreads();
    int found = 0;
    for (int i = threadIdx.x; i < TOTE/2 * 2; i += blockDim.x) {
        if (w[2*i + 1] != 0u) { found = 1; break; }
        if (2*i + 1 >= TOTE - 1) break;
    }
    if (found) atomicOr(&nz, 1);
    __syncthreads();
    if (threadIdx.x == 0) g_is64 = nz ? 0 : 1;
}

__device__ __forceinline__ int ldidx(const void* p, long long i) {
    return g_is64 ? (int)((const long long*)p)[i] : ((const int*)p)[i];
}

// ---------------- edge decode --------------------------------------------------
__device__ __forceinline__ void edge_decode(const void* ei, const void* et,
                                            const float* ew, int e,
                                            int& src, int& dst, int& rel, float& w) {
    if (e < NE) {
        src = ldidx(ei, e); dst = ldidx(ei, NE + e);
        rel = ldidx(et, e); w = ew[e];
    } else {
        int e2 = e - NE;
        src = ldidx(ei, NE + e2); dst = ldidx(ei, e2);
        rel = ldidx(et, e2) + 2;  w = ew[e2];
    }
}

// ---------------- zero small state ---------------------------------------------
__global__ void zero_small_kernel() {        // 98 blocks x 512
    int j = blockIdx.x*512 + threadIdx.x;
    g_cnt[j] = 0; g_cur[j] = 0;
    if (j < NN) g_deg[j] = 0.f;
}

// ---------------- CSR: count / scan / fill -------------------------------------
__global__ void count_kernel(const void* __restrict__ ei, const void* __restrict__ et,
                             const float* __restrict__ ew) {
    int e = blockIdx.x * blockDim.x + threadIdx.x;
    if (e >= TOTE) return;
    int src, dst, rel; float w;
    edge_decode(ei, et, ew, e, src, dst, rel, w);
    atomicAdd(&g_cnt[dst], 1);
    atomicAdd(&g_deg[dst], w);
}

__global__ void scan_sum_kernel() {          // 98 blocks x 512
    __shared__ int sh[512];
    int b = blockIdx.x, t = threadIdx.x;
    sh[t] = g_cnt[b*512 + t];
    __syncthreads();
    for (int s = 256; s > 0; s >>= 1) {
        if (t < s) sh[t] += sh[t+s];
        __syncthreads();
    }
    if (t == 0) g_bsum[b] = sh[0];
}

__global__ void scan_off_kernel() {          // 1 block x 128
    __shared__ int sh[128];
    int t = threadIdx.x;
    sh[t] = (t < SCAN_NB) ? g_bsum[t] : 0;
    __syncthreads();
    for (int s = 1; s < 128; s <<= 1) {
        int v = (t >= s) ? sh[t-s] : 0;
        __syncthreads();
        sh[t] += v;
        __syncthreads();
    }
    if (t < SCAN_NB) g_boff[t+1] = sh[t];
    if (t == 0) g_boff[0] = 0;
}

__global__ void scan_write_kernel() {        // 98 blocks x 512
    __shared__ int sh[512];
    int b = blockIdx.x, t = threadIdx.x;
    int j = b*512 + t;
    int c = g_cnt[j];
    sh[t] = c;
    __syncthreads();
    for (int s = 1; s < 512; s <<= 1) {
        int v = (t >= s) ? sh[t-s] : 0;
        __syncthreads();
        sh[t] += v;
        __syncthreads();
    }
    g_off[j] = g_boff[b] + sh[t] - c;        // exclusive start
}

__global__ void fill_kernel(const void* __restrict__ ei, const void* __restrict__ et,
                            const float* __restrict__ ew) {
    int e = blockIdx.x * blockDim.x + threadIdx.x;
    if (e >= TOTE) return;
    int src, dst, rel; float w;
    edge_decode(ei, et, ew, e, src, dst, rel, w);
    int pos = g_off[dst] + atomicAdd(&g_cur[dst], 1);
    g_epack[pos] = src | (rel << 17);
    g_eww[pos] = w;
}

// ---------------- input LayerNorm ---------------------------------------------
__global__ void input_ln_kernel(const float* __restrict__ nf, const void* __restrict__ ntype,
                                const float* __restrict__ emb, const float* __restrict__ gw,
                                const float* __restrict__ gb) {
    __shared__ float2 red[256];
    int row = blockIdx.x, t = threadIdx.x;
    int nt = ldidx(ntype, row);
    long long off = (long long)row * DIM;
    float v0 = nf[off + t]       + emb[nt*DIM + t];
    float v1 = nf[off + t + 256] + emb[nt*DIM + t + 256];
    red[t] = make_float2(v0 + v1, v0*v0 + v1*v1);
    __syncthreads();
    for (int s = 128; s > 0; s >>= 1) {
        if (t < s) { red[t].x += red[t+s].x; red[t].y += red[t+s].y; }
        __syncthreads();
    }
    float m = red[0].x * (1.f/DIM);
    float var = red[0].y * (1.f/DIM) - m*m;
    float r = rsqrtf(var + 1e-5f);
    float b0 = (v0 - m)*r*gw[t]     + gb[t];
    float b1 = (v1 - m)*r*gw[t+256] + gb[t+256];
    g_base[off + t]       = b0;
    g_base[off + t + 256] = b1;
    g_baseh[off + t]       = __float2half(b0);
    g_baseh[off + t + 256] = __float2half(b1);
}

// ---------------- weight convert ----------------------------------------------
__global__ void conv_w_kernel(const float* __restrict__ src, int n, int off) {
    for (int i = blockIdx.x*blockDim.x + threadIdx.x; i < n; i += gridDim.x*blockDim.x)
        g_wh[off + i] = __float2half(src[i]);
}

// ================= fp16 tensor-core GEMM (NT, mma.sync) =======================
#define GBM 128
#define GBN 128
#define GBK 32

__device__ __forceinline__ void ldsm4(uint32_t* r, uint32_t addr) {
    asm volatile("ldmatrix.sync.aligned.m8n8.x4.shared.b16 {%0,%1,%2,%3},[%4];\n"
        : "=r"(r[0]), "=r"(r[1]), "=r"(r[2]), "=r"(r[3]) : "r"(addr));
}
__device__ __forceinline__ void mma_f16(float* d, const uint32_t* a, uint32_t b0, uint32_t b1) {
    asm volatile("mma.sync.aligned.m16n8k16.row.col.f32.f16.f16.f32 "
        "{%0,%1,%2,%3},{%4,%5,%6,%7},{%8,%9},{%0,%1,%2,%3};\n"
        : "+f"(d[0]), "+f"(d[1]), "+f"(d[2]), "+f"(d[3])
        : "r"(a[0]), "r"(a[1]), "r"(a[2]), "r"(a[3]), "r"(b0), "r"(b1));
}
__device__ __forceinline__ void cp16(uint32_t dst, const void* src, int sz) {
    asm volatile("cp.async.cg.shared.global [%0],[%1],16,%2;\n" :: "r"(dst), "l"(src), "r"(sz));
}

// mode: 0 = fp32 C = acc (+bias if bias)   1 = fp16 O = acc + bias
//       2 = fp16 O = gelu(acc + bias)
__global__ void __launch_bounds__(128) gemm_f16(
    const __half* __restrict__ A, const __half* __restrict__ B,
    float* __restrict__ C, __half* __restrict__ O, const float* __restrict__ bias,
    int M, int N, int K, long long bStrideZ, long long outStrideZ, long long biasStrideZ, int mode)
{
    extern __shared__ __align__(1024) char smraw[];
    const int tid = threadIdx.x;
    const int lane = tid & 31, wid = tid >> 5;
    const int wm = wid >> 1, wn = wid & 1;
    const int bm = blockIdx.y * GBM, bn = blockIdx.x * GBN, z = blockIdx.z;
    const __half* Bz = B + (long long)z * bStrideZ;
    const int niter = K / GBK;
    uint32_t smbase = (uint32_t)__cvta_generic_to_shared(smraw);

    const int cc = tid & 3;
    const int rr = tid >> 2;
    long long arow[4];
    int avalid[4];
    #pragma unroll
    for (int i = 0; i < 4; i++) {
        int gr = bm + i*32 + rr;
        bool ok = (gr < M);
        arow[i] = (long long)(ok ? gr : 0) * K;
        avalid[i] = ok ? 16 : 0;
    }

    float acc[4][8][4];
    #pragma unroll
    for (int i = 0; i < 4; i++)
        #pragma unroll
        for (int j = 0; j < 8; j++)
            #pragma unroll
            for (int c = 0; c < 4; c++) acc[i][j][c] = 0.f;

    auto issue_copy = [&](int stage, int it) {
        int kb = it * GBK;
        #pragma unroll
        for (int i = 0; i < 4; i++) {
            int row = i*32 + rr;
            uint32_t dst = smbase + stage*16384
                         + (uint32_t)(row*64 + ((cc ^ ((row>>1)&3)) << 4));
            cp16(dst, A + arow[i] + kb + cc*8, avalid[i]);
        }
        #pragma unroll
        for (int i = 0; i < 4; i++) {
            int row = i*32 + rr;
            uint32_t dst = smbase + stage*16384 + 8192
                         + (uint32_t)(row*64 + ((cc ^ ((row>>1)&3)) << 4));
            cp16(dst, Bz + (long long)(bn + row)*K + kb + cc*8, 16);
        }
        asm volatile("cp.async.commit_group;\n" ::: "memory");
    };

    issue_copy(0, 0);

    for (int it = 0; it < niter; ++it) {
        if (it + 1 < niter) {
            issue_copy((it + 1) & 1, it + 1);
            asm volatile("cp.async.wait_group 1;\n" ::: "memory");
        } else {
            asm volatile("cp.async.wait_group 0;\n" ::: "memory");
        }
        __syncthreads();

        uint32_t sA = smbase + (it & 1)*16384;
        uint32_t sB = sA + 8192;
        int rsel = lane & 15;
        #pragma unroll
        for (int kk = 0; kk < 2; kk++) {
            int csel = kk*2 + (lane >> 4);
            uint32_t ah[4][4], bh[4][4];
            #pragma unroll
            for (int mi = 0; mi < 4; mi++) {
                int row = wm*64 + mi*16 + rsel;
                uint32_t off = (uint32_t)(row*64 + ((csel ^ ((row>>1)&3)) << 4));
                ldsm4(ah[mi], sA + off);
            }
            #pragma unroll
            for (int p = 0; p < 4; p++) {
                int row = wn*64 + p*16 + rsel;
                uint32_t off = (uint32_t)(row*64 + ((csel ^ ((row>>1)&3)) << 4));
                ldsm4(bh[p], sB + off);
            }
            #pragma unroll
            for (int mi = 0; mi < 4; mi++)
                #pragma unroll
                for (int nj = 0; nj < 8; nj++) {
                    int p = nj >> 1, h = nj & 1;
                    mma_f16(acc[mi][nj], ah[mi], bh[p][h], bh[p][2+h]);
                }
        }
        __syncthreads();
    }

    // ---- epilogue -----------------------------------------------------------
    #pragma unroll
    for (int mi = 0; mi < 4; mi++) {
        #pragma unroll
        for (int nj = 0; nj < 8; nj++) {
            int gc = bn + wn*64 + nj*8 + (lane & 3)*2;
            #pragma unroll
            for (int half = 0; half < 2; half++) {
                int gr = bm + wm*64 + mi*16 + (lane >> 2) + half*8;
                if (gr >= M) continue;
                float v0 = acc[mi][nj][half*2 + 0];
                float v1 = acc[mi][nj][half*2 + 1];
                if (mode == 0) {
                    if (bias) {
                        const float* bs = bias + (long long)z*biasStrideZ;
                        v0 += bs[gc]; v1 += bs[gc+1];
                    }
                    float* Cp = C + (long long)z*outStrideZ + (long long)gr*N + gc;
                    float2 w2 = make_float2(v0, v1);
                    *(float2*)Cp = w2;
                } else {
                    const float* bs = bias + (long long)z*biasStrideZ;
                    v0 += bs[gc]; v1 += bs[gc+1];
                    if (mode == 2) {
                        v0 = 0.5f * v0 * (1.f + erff(v0 * 0.70710678118654752f));
                        v1 = 0.5f * v1 * (1.f + erff(v1 * 0.70710678118654752f));
                    }
                    __half2 o;
                    o.x = __float2half(v0);
                    o.y = __float2half(v1);
                    *(__half2*)(O + (long long)z*outStrideZ + (long long)gr*N + gc) = o;
                }
            }
        }
    }
}

// ---------------- fused CSR gather + LN1 ---------------------------------------
// x1h = fp16( LN( base + (sum_j w_j * y[rel_j][src_j]) / max(deg,1) + selfh ) )
__global__ void __launch_bounds__(128) gather_ln1_kernel(
    const float* __restrict__ gw, const float* __restrict__ gb) {
    __shared__ float2 red[128];
    int n = blockIdx.x, t = threadIdx.x;
    int off = g_off[n], cnt = g_cnt[n];
    float a0 = 0.f, a1 = 0.f, a2 = 0.f, a3 = 0.f;
    for (int j = off; j < off + cnt; j++) {
        int pk = g_epack[j];
        float w = g_eww[j];
        int src = pk & 0x1FFFF, rel = pk >> 17;
        uint2 p = *(const uint2*)(g_yh + ((long long)rel*NN + src)*DIM + t*4);
        __half2 h0 = *(__half2*)&p.x, h1 = *(__half2*)&p.y;
        a0 += w * __half2float(h0.x);
        a1 += w * __half2float(h0.y);
        a2 += w * __half2float(h1.x);
        a3 += w * __half2float(h1.y);
    }
    float inv = 1.f / fmaxf(g_deg[n], 1.f);
    long long o = (long long)n * DIM + t*4;
    float4 bs = *(const float4*)(g_base + o);
    uint2 sp = *(const uint2*)(g_selfh + o);
    __half2 s0 = *(__half2*)&sp.x, s1 = *(__half2*)&sp.y;
    float v0 = bs.x + a0*inv + __half2float(s0.x);
    float v1 = bs.y + a1*inv + __half2float(s0.y);
    float v2 = bs.z + a2*inv + __half2float(s1.x);
    float v3 = bs.w + a3*inv + __half2float(s1.y);
    red[t] = make_float2(v0+v1+v2+v3, v0*v0+v1*v1+v2*v2+v3*v3);
    __syncthreads();
    for (int s = 64; s > 0; s >>= 1) {
        if (t < s) { red[t].x += red[t+s].x; red[t].y += red[t+s].y; }
        __syncthreads();
    }
    float m = red[0].x * (1.f/DIM);
    float var = red[0].y * (1.f/DIM) - m*m;
    float r = rsqrtf(var + 1e-5f);
    int c = t*4;
    __half2 o0, o1;
    o0.x = __float2half((v0 - m)*r*gw[c]   + gb[c]);
    o0.y = __float2half((v1 - m)*r*gw[c+1] + gb[c+1]);
    o1.x = __float2half((v2 - m)*r*gw[c+2] + gb[c+2]);
    o1.y = __float2half((v3 - m)*r*gw[c+3] + gb[c+3]);
    uint2 outp;
    *(__half2*)&outp.x = o0;
    *(__half2*)&outp.y = o1;
    *(uint2*)(g_x1h + o) = outp;
}

// ---------------- final fused: LN2 -> out-LN -> graph mix ---------------------
__global__ void final_fuse_kernel(const float* __restrict__ bf2,
                                  const float* __restrict__ n2g, const float* __restrict__ n2b,
                                  const float* __restrict__ og,  const float* __restrict__ ob,
                                  const float* __restrict__ gml, float* __restrict__ out) {
    __shared__ float2 red[256];
    int row = blockIdx.x, t = threadIdx.x;
    long long off = (long long)row * DIM;
    float t0 = __half2float(g_x1h[off+t])     + g_agg[off+t]     + bf2[t];
    float t1 = __half2float(g_x1h[off+t+256]) + g_agg[off+t+256] + bf2[t+256];
    red[t] = make_float2(t0 + t1, t0*t0 + t1*t1);
    __syncthreads();
    for (int s = 128; s > 0; s >>= 1) {
        if (t < s) { red[t].x += red[t+s].x; red[t].y += red[t+s].y; }
        __syncthreads();
    }
    float m = red[0].x * (1.f/DIM);
    float var = red[0].y * (1.f/DIM) - m*m;
    float r = rsqrtf(var + 1e-5f);
    float x20 = (t0 - m)*r*n2g[t]     + n2b[t];
    float x21 = (t1 - m)*r*n2g[t+256] + n2b[t+256];
    __syncthreads();
    red[t] = make_float2(x20 + x21, x20*x20 + x21*x21);
    __syncthreads();
    for (int s = 128; s > 0; s >>= 1) {
        if (t < s) { red[t].x += red[t+s].x; red[t].y += red[t+s].y; }
        __syncthreads();
    }
    m = red[0].x * (1.f/DIM);
    var = red[0].y * (1.f/DIM) - m*m;
    r = rsqrtf(var + 1e-5f);
    float x30 = (x20 - m)*r*og[t]     + ob[t];
    float x31 = (x21 - m)*r*og[t+256] + ob[t+256];
    float gm = 1.f / (1.f + expf(-gml[0]));
    float b0 = g_base[off+t], b1 = g_base[off+t+256];
    out[off+t]     = b0 + gm*(x30 - b0);
    out[off+t+256] = b1 + gm*(x31 - b1);
}

// ---------------- pooling -----------------------------------------------------
__global__ void pool_part_kernel(const float* __restrict__ x) {
    int b = blockIdx.x;
    int t = threadIdx.x;
    float s = 0.f;
    for (int r = b; r < NN; r += 256)
        s += x[(long long)r*DIM + t];
    g_part[b*DIM + t] = s;
}

__global__ void pool_final_kernel(const float* __restrict__ x, const float* __restrict__ dml,
                                  float* __restrict__ pooled) {
    int t = threadIdx.x;
    float s = 0.f;
    for (int b = 0; b < 256; ++b) s += g_part[b*DIM + t];
    float mean = s * (1.f / NN);
    float dm = 1.f / (1.f + expf(-dml[0]));
    pooled[t] = dm * x[t] + (1.f - dm) * mean;
}

// ---------------- host launcher ----------------------------------------------
extern "C" void kernel_launch(void* const* d_in, const int* in_sizes, int n_in,
                              void* d_out, int out_size) {
    (void)in_sizes; (void)n_in; (void)out_size;
    const float* nf     = (const float*)d_in[0];
    const void*  ei     = d_in[1];
    const void*  et     = d_in[2];
    const void*  ntype  = d_in[3];
    const float* ew     = (const float*)d_in[4];
    const float* emb    = (const float*)d_in[5];
    const float* W_self = (const float*)d_in[6];
    const float* b_self = (const float*)d_in[7];
    const float* W_rel  = (const float*)d_in[8];
    const float* b_rel  = (const float*)d_in[9];
    const float* in_g   = (const float*)d_in[10];
    const float* in_b   = (const float*)d_in[11];
    const float* n1_g   = (const float*)d_in[12];
    const float* n1_b   = (const float*)d_in[13];
    const float* Wf1    = (const float*)d_in[14];
    const float* bf1    = (const float*)d_in[15];
    const float* Wf2    = (const float*)d_in[16];
    const float* bf2    = (const float*)d_in[17];
    const float* n2_g   = (const float*)d_in[18];
    const float* n2_b   = (const float*)d_in[19];
    const float* out_g  = (const float*)d_in[20];
    const float* out_b  = (const float*)d_in[21];
    const float* gml    = (const float*)d_in[22];
    const float* dml    = (const float*)d_in[23];
    float* out = (float*)d_out;

    static bool init = false;
    static float *p_agg;
    static __half *p_yh, *p_bh, *p_selfh, *p_x1h, *p_uh, *p_wh;
    if (!init) {
        cudaGetSymbolAddress((void**)&p_yh,    g_yh);
        cudaGetSymbolAddress((void**)&p_agg,   g_agg);
        cudaGetSymbolAddress((void**)&p_selfh, g_selfh);
        cudaGetSymbolAddress((void**)&p_bh,    g_baseh);
        cudaGetSymbolAddress((void**)&p_x1h,   g_x1h);
        cudaGetSymbolAddress((void**)&p_uh,    g_uh);
        cudaGetSymbolAddress((void**)&p_wh,    g_wh);
        init = true;
    }

    const int MROWS = (NN + GBM - 1) / GBM;   // 391
    const int SMEMB = 32768;

    detect_idx_kernel<<<1, 256>>>((const unsigned int*)ei);
    zero_small_kernel<<<SCAN_NB, 512>>>();
    input_ln_kernel<<<NN, 256>>>(nf, ntype, emb, in_g, in_b);
    conv_w_kernel<<<2048, 256>>>(W_rel,  NRELS*DIM*DIM, WREL_OFF);
    conv_w_kernel<<<512,  256>>>(W_self, DIM*DIM,       WSELF_OFF);
    conv_w_kernel<<<1024, 256>>>(Wf1,    FFDIM*DIM,     WF1_OFF);
    conv_w_kernel<<<1024, 256>>>(Wf2,    DIM*FFDIM,     WF2_OFF);

    // CSR build
    count_kernel<<<(TOTE + 255)/256, 256>>>(ei, et, ew);
    scan_sum_kernel<<<SCAN_NB, 512>>>();
    scan_off_kernel<<<1, 128>>>();
    scan_write_kernel<<<SCAN_NB, 512>>>();
    fill_kernel<<<(TOTE + 255)/256, 256>>>(ei, et, ew);

    // y[rel] = fp16(base @ W_rel[rel].T + b_rel[rel])
    {
        dim3 grid(DIM / GBN, MROWS, NRELS);
        gemm_f16<<<grid, 128, SMEMB>>>(p_bh, p_wh + WREL_OFF, nullptr, p_yh, b_rel,
                                       NN, DIM, DIM, (long long)DIM*DIM,
                                       (long long)NN*DIM, DIM, 1);
    }
    // selfh = fp16(base @ W_self.T + b_self)
    {
        dim3 grid(DIM / GBN, MROWS, 1);
        gemm_f16<<<grid, 128, SMEMB>>>(p_bh, p_wh + WSELF_OFF, nullptr, p_selfh, b_self,
                                       NN, DIM, DIM, 0, 0, 0, 1);
    }
    // fused CSR gather + LN1
    gather_ln1_kernel<<<NN, 128>>>(n1_g, n1_b);

    // FFN1 (+bias+gelu fused, fp16 output)
    {
        dim3 grid(FFDIM / GBN, MROWS, 1);
        gemm_f16<<<grid, 128, SMEMB>>>(p_x1h, p_wh + WF1_OFF, nullptr, p_uh, bf1,
                                       NN, FFDIM, DIM, 0, 0, 0, 2);
    }
    // FFN2 -> g_agg fp32 (bf2 added in final_fuse)
    {
        dim3 grid(DIM / GBN, MROWS, 1);
        gemm_f16<<<grid, 128, SMEMB>>>(p_uh, p_wh + WF2_OFF, p_agg, nullptr, nullptr,
                                       NN, DIM, FFDIM, 0, 0, 0, 0);
    }

    final_fuse_kernel<<<NN, 256>>>(bf2, n2_g, n2_b, out_g, out_b, gml, out);
    pool_part_kernel<<<256, 512>>>(out);
    pool_final_kernel<<<1, 512>>>(out, dml, out + (long long)NN*DIM);
}

// round 16
// speedup vs baseline: 1.1504x; 1.0556x over previous
#include <cuda_runtime.h>
#include <cuda_fp16.h>
#include <math.h>
#include <stdint.h>

#define DIM 512
#define NN 50000
#define NE 100000
#define TOTE (2*NE)
#define NRELS 4
#define FFDIM 1024
#define NNP 50176              // 98*512 padded node count for scan
#define SCAN_NB 98

// ---------------- scratch (device globals; no allocation allowed) -------------
__device__ __half g_yh[NRELS*NN*DIM];    // per-rel transformed nodes (fp16)
__device__ float g_deg[NN];
__device__ float g_base[NN*DIM];
__device__ __half g_baseh[NN*DIM];
__device__ float g_agg[NN*DIM];          // FFN2 output
__device__ __half g_selfh[NN*DIM];       // base@Wself.T + b_self (fp16)
__device__ __half g_x1h[NN*DIM];
__device__ __half g_uh[NN*FFDIM];        // FFN hidden (post-gelu) fp16
#define NWELEM 2359296
#define WREL_OFF 0
#define WSELF_OFF 1048576
#define WF1_OFF 1310720
#define WF2_OFF 1835008
__device__ __half g_wh[NWELEM];
__device__ float g_part[256*DIM];
__device__ int   g_is64;
// CSR state
__device__ int   g_cnt[NNP];
__device__ int   g_cur[NNP];
__device__ int   g_off[NNP];
__device__ int   g_bsum[SCAN_NB];
__device__ int   g_boff[SCAN_NB+2];
__device__ int   g_epack[TOTE];          // src | (rel<<17)
__device__ float g_eww[TOTE];

// ---------------- index dtype detection --------------------------------------
__global__ void detect_idx_kernel(const unsigned int* __restrict__ w) {
    __shared__ int nz;
    if (threadIdx.x == 0) nz = 0;
    __syncthreads();
    int found = 0;
    for (int i = threadIdx.x; i < TOTE/2 * 2; i += blockDim.x) {
        if (w[2*i + 1] != 0u) { found = 1; break; }
        if (2*i + 1 >= TOTE - 1) break;
    }
    if (found) atomicOr(&nz, 1);
    __syncthreads();
    if (threadIdx.x == 0) g_is64 = nz ? 0 : 1;
}

__device__ __forceinline__ int ldidx(const void* p, long long i) {
    return g_is64 ? (int)((const long long*)p)[i] : ((const int*)p)[i];
}

// ---------------- edge decode --------------------------------------------------
__device__ __forceinline__ void edge_decode(const void* ei, const void* et,
                                            const float* ew, int e,
                                            int& src, int& dst, int& rel, float& w) {
    if (e < NE) {
        src = ldidx(ei, e); dst = ldidx(ei, NE + e);
        rel = ldidx(et, e); w = ew[e];
    } else {
        int e2 = e - NE;
        src = ldidx(ei, NE + e2); dst = ldidx(ei, e2);
        rel = ldidx(et, e2) + 2;  w = ew[e2];
    }
}

// ---------------- zero small state ---------------------------------------------
__global__ void zero_small_kernel() {        // 98 blocks x 512
    int j = blockIdx.x*512 + threadIdx.x;
    g_cnt[j] = 0; g_cur[j] = 0;
    if (j < NN) g_deg[j] = 0.f;
}

// ---------------- CSR: count / scan / fill -------------------------------------
__global__ void count_kernel(const void* __restrict__ ei, const void* __restrict__ et,
                             const float* __restrict__ ew) {
    int e = blockIdx.x * blockDim.x + threadIdx.x;
    if (e >= TOTE) return;
    int src, dst, rel; float w;
    edge_decode(ei, et, ew, e, src, dst, rel, w);
    atomicAdd(&g_cnt[dst], 1);
    atomicAdd(&g_deg[dst], w);
}

__global__ void scan_sum_kernel() {          // 98 blocks x 512
    __shared__ int sh[512];
    int b = blockIdx.x, t = threadIdx.x;
    sh[t] = g_cnt[b*512 + t];
    __syncthreads();
    for (int s = 256; s > 0; s >>= 1) {
        if (t < s) sh[t] += sh[t+s];
        __syncthreads();
    }
    if (t == 0) g_bsum[b] = sh[0];
}

__global__ void scan_off_kernel() {          // 1 block x 128
    __shared__ int sh[128];
    int t = threadIdx.x;
    sh[t] = (t < SCAN_NB) ? g_bsum[t] : 0;
    __syncthreads();
    for (int s = 1; s < 128; s <<= 1) {
        int v = (t >= s) ? sh[t-s] : 0;
        __syncthreads();
        sh[t] += v;
        __syncthreads();
    }
    if (t < SCAN_NB) g_boff[t+1] = sh[t];
    if (t == 0) g_boff[0] = 0;
}

__global__ void scan_write_kernel() {        // 98 blocks x 512
    __shared__ int sh[512];
    int b = blockIdx.x, t = threadIdx.x;
    int j = b*512 + t;
    int c = g_cnt[j];
    sh[t] = c;
    __syncthreads();
    for (int s = 1; s < 512; s <<= 1) {
        int v = (t >= s) ? sh[t-s] : 0;
        __syncthreads();
        sh[t] += v;
        __syncthreads();
    }
    g_off[j] = g_boff[b] + sh[t] - c;        // exclusive start
}

__global__ void fill_kernel(const void* __restrict__ ei, const void* __restrict__ et,
                            const float* __restrict__ ew) {
    int e = blockIdx.x * blockDim.x + threadIdx.x;
    if (e >= TOTE) return;
    int src, dst, rel; float w;
    edge_decode(ei, et, ew, e, src, dst, rel, w);
    int pos = g_off[dst] + atomicAdd(&g_cur[dst], 1);
    g_epack[pos] = src | (rel << 17);
    g_eww[pos] = w;
}

// ---------------- input LayerNorm ---------------------------------------------
__global__ void input_ln_kernel(const float* __restrict__ nf, const void* __restrict__ ntype,
                                const float* __restrict__ emb, const float* __restrict__ gw,
                                const float* __restrict__ gb) {
    __shared__ float2 red[256];
    int row = blockIdx.x, t = threadIdx.x;
    int nt = ldidx(ntype, row);
    long long off = (long long)row * DIM;
    float v0 = nf[off + t]       + emb[nt*DIM + t];
    float v1 = nf[off + t + 256] + emb[nt*DIM + t + 256];
    red[t] = make_float2(v0 + v1, v0*v0 + v1*v1);
    __syncthreads();
    for (int s = 128; s > 0; s >>= 1) {
        if (t < s) { red[t].x += red[t+s].x; red[t].y += red[t+s].y; }
        __syncthreads();
    }
    float m = red[0].x * (1.f/DIM);
    float var = red[0].y * (1.f/DIM) - m*m;
    float r = rsqrtf(var + 1e-5f);
    float b0 = (v0 - m)*r*gw[t]     + gb[t];
    float b1 = (v1 - m)*r*gw[t+256] + gb[t+256];
    g_base[off + t]       = b0;
    g_base[off + t + 256] = b1;
    g_baseh[off + t]       = __float2half(b0);
    g_baseh[off + t + 256] = __float2half(b1);
}

// ---------------- weight convert ----------------------------------------------
__global__ void conv_w_kernel(const float* __restrict__ src, int n, int off) {
    for (int i = blockIdx.x*blockDim.x + threadIdx.x; i < n; i += gridDim.x*blockDim.x)
        g_wh[off + i] = __float2half(src[i]);
}

// ================= fp16 tensor-core GEMM (NT, mma.sync) =======================
// 256 threads, 8 warps (warp tile 32x64), 3-stage cp.async pipeline.
#define GBM 128
#define GBN 128
#define GBK 32
#define STG 16384

__device__ __forceinline__ void ldsm4(uint32_t* r, uint32_t addr) {
    asm volatile("ldmatrix.sync.aligned.m8n8.x4.shared.b16 {%0,%1,%2,%3},[%4];\n"
        : "=r"(r[0]), "=r"(r[1]), "=r"(r[2]), "=r"(r[3]) : "r"(addr));
}
__device__ __forceinline__ void mma_f16(float* d, const uint32_t* a, uint32_t b0, uint32_t b1) {
    asm volatile("mma.sync.aligned.m16n8k16.row.col.f32.f16.f16.f32 "
        "{%0,%1,%2,%3},{%4,%5,%6,%7},{%8,%9},{%0,%1,%2,%3};\n"
        : "+f"(d[0]), "+f"(d[1]), "+f"(d[2]), "+f"(d[3])
        : "r"(a[0]), "r"(a[1]), "r"(a[2]), "r"(a[3]), "r"(b0), "r"(b1));
}
__device__ __forceinline__ void cp16(uint32_t dst, const void* src, int sz) {
    asm volatile("cp.async.cg.shared.global [%0],[%1],16,%2;\n" :: "r"(dst), "l"(src), "r"(sz));
}

// mode: 0 = fp32 C = acc (+bias if bias)   1 = fp16 O = acc + bias
//       2 = fp16 O = gelu(acc + bias)
__global__ void __launch_bounds__(256) gemm_f16(
    const __half* __restrict__ A, const __half* __restrict__ B,
    float* __restrict__ C, __half* __restrict__ O, const float* __restrict__ bias,
    int M, int N, int K, long long bStrideZ, long long outStrideZ, long long biasStrideZ, int mode)
{
    extern __shared__ __align__(1024) char smraw[];
    const int tid = threadIdx.x;
    const int lane = tid & 31, wid = tid >> 5;
    const int wm = wid & 3, wn = wid >> 2;        // warp grid 4(M) x 2(N)
    const int bm = blockIdx.y * GBM, bn = blockIdx.x * GBN, z = blockIdx.z;
    const __half* Bz = B + (long long)z * bStrideZ;
    const int niter = K / GBK;
    uint32_t smbase = (uint32_t)__cvta_generic_to_shared(smraw);

    const int cc = tid & 3;          // 16B chunk within a 64B k-slice
    const int rr = tid >> 2;         // 0..63
    long long arow[2];
    int avalid[2];
    #pragma unroll
    for (int i = 0; i < 2; i++) {
        int gr = bm + i*64 + rr;
        bool ok = (gr < M);
        arow[i] = (long long)(ok ? gr : 0) * K;
        avalid[i] = ok ? 16 : 0;
    }

    float acc[2][8][4];
    #pragma unroll
    for (int i = 0; i < 2; i++)
        #pragma unroll
        for (int j = 0; j < 8; j++)
            #pragma unroll
            for (int c = 0; c < 4; c++) acc[i][j][c] = 0.f;

    auto issue_copy = [&](int stage, int it) {
        int kb = it * GBK;
        #pragma unroll
        for (int i = 0; i < 2; i++) {
            int row = i*64 + rr;
            uint32_t dst = smbase + stage*STG
                         + (uint32_t)(row*64 + ((cc ^ ((row>>1)&3)) << 4));
            cp16(dst, A + arow[i] + kb + cc*8, avalid[i]);
        }
        #pragma unroll
        for (int i = 0; i < 2; i++) {
            int row = i*64 + rr;
            uint32_t dst = smbase + stage*STG + 8192
                         + (uint32_t)(row*64 + ((cc ^ ((row>>1)&3)) << 4));
            cp16(dst, Bz + (long long)(bn + row)*K + kb + cc*8, 16);
        }
        asm volatile("cp.async.commit_group;\n" ::: "memory");
    };

    issue_copy(0, 0);
    if (niter > 1) issue_copy(1, 1);

    int stage = 0;
    for (int it = 0; it < niter; ++it) {
        if (it + 2 < niter) {
            int s2 = stage + 2; if (s2 >= 3) s2 -= 3;
            issue_copy(s2, it + 2);
            asm volatile("cp.async.wait_group 2;\n" ::: "memory");
        } else if (it + 1 < niter) {
            asm volatile("cp.async.wait_group 1;\n" ::: "memory");
        } else {
            asm volatile("cp.async.wait_group 0;\n" ::: "memory");
        }
        __syncthreads();

        uint32_t sA = smbase + stage*STG;
        uint32_t sB = sA + 8192;
        int rsel = lane & 15;
        #pragma unroll
        for (int kk = 0; kk < 2; kk++) {
            int csel = kk*2 + (lane >> 4);
            uint32_t ah[2][4], bh[4][4];
            #pragma unroll
            for (int mi = 0; mi < 2; mi++) {
                int row = wm*32 + mi*16 + rsel;
                uint32_t off = (uint32_t)(row*64 + ((csel ^ ((row>>1)&3)) << 4));
                ldsm4(ah[mi], sA + off);
            }
            #pragma unroll
            for (int p = 0; p < 4; p++) {
                int row = wn*64 + p*16 + rsel;
                uint32_t off = (uint32_t)(row*64 + ((csel ^ ((row>>1)&3)) << 4));
                ldsm4(bh[p], sB + off);
            }
            #pragma unroll
            for (int mi = 0; mi < 2; mi++)
                #pragma unroll
                for (int nj = 0; nj < 8; nj++) {
                    int p = nj >> 1, h = nj & 1;
                    mma_f16(acc[mi][nj], ah[mi], bh[p][h], bh[p][2+h]);
                }
        }
        __syncthreads();
        if (++stage == 3) stage = 0;
    }

    // ---- epilogue -----------------------------------------------------------
    #pragma unroll
    for (int mi = 0; mi < 2; mi++) {
        #pragma unroll
        for (int nj = 0; nj < 8; nj++) {
            int gc = bn + wn*64 + nj*8 + (lane & 3)*2;
            #pragma unroll
            for (int half = 0; half < 2; half++) {
                int gr = bm + wm*32 + mi*16 + (lane >> 2) + half*8;
                if (gr >= M) continue;
                float v0 = acc[mi][nj][half*2 + 0];
                float v1 = acc[mi][nj][half*2 + 1];
                if (mode == 0) {
                    if (bias) {
                        const float* bs = bias + (long long)z*biasStrideZ;
                        v0 += bs[gc]; v1 += bs[gc+1];
                    }
                    float* Cp = C + (long long)z*outStrideZ + (long long)gr*N + gc;
                    float2 w2 = make_float2(v0, v1);
                    *(float2*)Cp = w2;
                } else {
                    const float* bs = bias + (long long)z*biasStrideZ;
                    v0 += bs[gc]; v1 += bs[gc+1];
                    if (mode == 2) {
                        v0 = 0.5f * v0 * (1.f + erff(v0 * 0.70710678118654752f));
                        v1 = 0.5f * v1 * (1.f + erff(v1 * 0.70710678118654752f));
                    }
                    __half2 o;
                    o.x = __float2half(v0);
                    o.y = __float2half(v1);
                    *(__half2*)(O + (long long)z*outStrideZ + (long long)gr*N + gc) = o;
                }
            }
        }
    }
}

// ---------------- fused CSR gather + LN1 ---------------------------------------
__global__ void __launch_bounds__(128) gather_ln1_kernel(
    const float* __restrict__ gw, const float* __restrict__ gb) {
    __shared__ float2 red[128];
    int n = blockIdx.x, t = threadIdx.x;
    int off = g_off[n], cnt = g_cnt[n];
    float a0 = 0.f, a1 = 0.f, a2 = 0.f, a3 = 0.f;
    for (int j = off; j < off + cnt; j++) {
        int pk = g_epack[j];
        float w = g_eww[j];
        int src = pk & 0x1FFFF, rel = pk >> 17;
        uint2 p = *(const uint2*)(g_yh + ((long long)rel*NN + src)*DIM + t*4);
        __half2 h0 = *(__half2*)&p.x, h1 = *(__half2*)&p.y;
        a0 += w * __half2float(h0.x);
        a1 += w * __half2float(h0.y);
        a2 += w * __half2float(h1.x);
        a3 += w * __half2float(h1.y);
    }
    float inv = 1.f / fmaxf(g_deg[n], 1.f);
    long long o = (long long)n * DIM + t*4;
    float4 bs = *(const float4*)(g_base + o);
    uint2 sp = *(const uint2*)(g_selfh + o);
    __half2 s0 = *(__half2*)&sp.x, s1 = *(__half2*)&sp.y;
    float v0 = bs.x + a0*inv + __half2float(s0.x);
    float v1 = bs.y + a1*inv + __half2float(s0.y);
    float v2 = bs.z + a2*inv + __half2float(s1.x);
    float v3 = bs.w + a3*inv + __half2float(s1.y);
    red[t] = make_float2(v0+v1+v2+v3, v0*v0+v1*v1+v2*v2+v3*v3);
    __syncthreads();
    for (int s = 64; s > 0; s >>= 1) {
        if (t < s) { red[t].x += red[t+s].x; red[t].y += red[t+s].y; }
        __syncthreads();
    }
    float m = red[0].x * (1.f/DIM);
    float var = red[0].y * (1.f/DIM) - m*m;
    float r = rsqrtf(var + 1e-5f);
    int c = t*4;
    __half2 o0, o1;
    o0.x = __float2half((v0 - m)*r*gw[c]   + gb[c]);
    o0.y = __float2half((v1 - m)*r*gw[c+1] + gb[c+1]);
    o1.x = __float2half((v2 - m)*r*gw[c+2] + gb[c+2]);
    o1.y = __float2half((v3 - m)*r*gw[c+3] + gb[c+3]);
    uint2 outp;
    *(__half2*)&outp.x = o0;
    *(__half2*)&outp.y = o1;
    *(uint2*)(g_x1h + o) = outp;
}

// ---------------- final fused: LN2 -> out-LN -> graph mix ---------------------
__global__ void final_fuse_kernel(const float* __restrict__ bf2,
                                  const float* __restrict__ n2g, const float* __restrict__ n2b,
                                  const float* __restrict__ og,  const float* __restrict__ ob,
                                  const float* __restrict__ gml, float* __restrict__ out) {
    __shared__ float2 red[256];
    int row = blockIdx.x, t = threadIdx.x;
    long long off = (long long)row * DIM;
    float t0 = __half2float(g_x1h[off+t])     + g_agg[off+t]     + bf2[t];
    float t1 = __half2float(g_x1h[off+t+256]) + g_agg[off+t+256] + bf2[t+256];
    red[t] = make_float2(t0 + t1, t0*t0 + t1*t1);
    __syncthreads();
    for (int s = 128; s > 0; s >>= 1) {
        if (t < s) { red[t].x += red[t+s].x; red[t].y += red[t+s].y; }
        __syncthreads();
    }
    float m = red[0].x * (1.f/DIM);
    float var = red[0].y * (1.f/DIM) - m*m;
    float r = rsqrtf(var + 1e-5f);
    float x20 = (t0 - m)*r*n2g[t]     + n2b[t];
    float x21 = (t1 - m)*r*n2g[t+256] + n2b[t+256];
    __syncthreads();
    red[t] = make_float2(x20 + x21, x20*x20 + x21*x21);
    __syncthreads();
    for (int s = 128; s > 0; s >>= 1) {
        if (t < s) { red[t].x += red[t+s].x; red[t].y += red[t+s].y; }
        __syncthreads();
    }
    m = red[0].x * (1.f/DIM);
    var = red[0].y * (1.f/DIM) - m*m;
    r = rsqrtf(var + 1e-5f);
    float x30 = (x20 - m)*r*og[t]     + ob[t];
    float x31 = (x21 - m)*r*og[t+256] + ob[t+256];
    float gm = 1.f / (1.f + expf(-gml[0]));
    float b0 = g_base[off+t], b1 = g_base[off+t+256];
    out[off+t]     = b0 + gm*(x30 - b0);
    out[off+t+256] = b1 + gm*(x31 - b1);
}

// ---------------- pooling -----------------------------------------------------
__global__ void pool_part_kernel(const float* __restrict__ x) {
    int b = blockIdx.x;
    int t = threadIdx.x;
    float s = 0.f;
    for (int r = b; r < NN; r += 256)
        s += x[(long long)r*DIM + t];
    g_part[b*DIM + t] = s;
}

__global__ void pool_final_kernel(const float* __restrict__ x, const float* __restrict__ dml,
                                  float* __restrict__ pooled) {
    int t = threadIdx.x;
    float s = 0.f;
    for (int b = 0; b < 256; ++b) s += g_part[b*DIM + t];
    float mean = s * (1.f / NN);
    float dm = 1.f / (1.f + expf(-dml[0]));
    pooled[t] = dm * x[t] + (1.f - dm) * mean;
}

// ---------------- host launcher ----------------------------------------------
extern "C" void kernel_launch(void* const* d_in, const int* in_sizes, int n_in,
                              void* d_out, int out_size) {
    (void)in_sizes; (void)n_in; (void)out_size;
    const float* nf     = (const float*)d_in[0];
    const void*  ei     = d_in[1];
    const void*  et     = d_in[2];
    const void*  ntype  = d_in[3];
    const float* ew     = (const float*)d_in[4];
    const float* emb    = (const float*)d_in[5];
    const float* W_self = (const float*)d_in[6];
    const float* b_self = (const float*)d_in[7];
    const float* W_rel  = (const float*)d_in[8];
    const float* b_rel  = (const float*)d_in[9];
    const float* in_g   = (const float*)d_in[10];
    const float* in_b   = (const float*)d_in[11];
    const float* n1_g   = (const float*)d_in[12];
    const float* n1_b   = (const float*)d_in[13];
    const float* Wf1    = (const float*)d_in[14];
    const float* bf1    = (const float*)d_in[15];
    const float* Wf2    = (const float*)d_in[16];
    const float* bf2    = (const float*)d_in[17];
    const float* n2_g   = (const float*)d_in[18];
    const float* n2_b   = (const float*)d_in[19];
    const float* out_g  = (const float*)d_in[20];
    const float* out_b  = (const float*)d_in[21];
    const float* gml    = (const float*)d_in[22];
    const float* dml    = (const float*)d_in[23];
    float* out = (float*)d_out;

    static bool init = false;
    static float *p_agg;
    static __half *p_yh, *p_bh, *p_selfh, *p_x1h, *p_uh, *p_wh;
    if (!init) {
        cudaGetSymbolAddress((void**)&p_yh,    g_yh);
        cudaGetSymbolAddress((void**)&p_agg,   g_agg);
        cudaGetSymbolAddress((void**)&p_selfh, g_selfh);
        cudaGetSymbolAddress((void**)&p_bh,    g_baseh);
        cudaGetSymbolAddress((void**)&p_x1h,   g_x1h);
        cudaGetSymbolAddress((void**)&p_uh,    g_uh);
        cudaGetSymbolAddress((void**)&p_wh,    g_wh);
        init = true;
    }

    const int MROWS = (NN + GBM - 1) / GBM;   // 391
    const int SMEMB = 3*STG;                  // 49152 (48KB)

    detect_idx_kernel<<<1, 256>>>((const unsigned int*)ei);
    zero_small_kernel<<<SCAN_NB, 512>>>();
    input_ln_kernel<<<NN, 256>>>(nf, ntype, emb, in_g, in_b);
    conv_w_kernel<<<2048, 256>>>(W_rel,  NRELS*DIM*DIM, WREL_OFF);
    conv_w_kernel<<<512,  256>>>(W_self, DIM*DIM,       WSELF_OFF);
    conv_w_kernel<<<1024, 256>>>(Wf1,    FFDIM*DIM,     WF1_OFF);
    conv_w_kernel<<<1024, 256>>>(Wf2,    DIM*FFDIM,     WF2_OFF);

    // CSR build
    count_kernel<<<(TOTE + 255)/256, 256>>>(ei, et, ew);
    scan_sum_kernel<<<SCAN_NB, 512>>>();
    scan_off_kernel<<<1, 128>>>();
    scan_write_kernel<<<SCAN_NB, 512>>>();
    fill_kernel<<<(TOTE + 255)/256, 256>>>(ei, et, ew);

    // y[rel] = fp16(base @ W_rel[rel].T + b_rel[rel])
    {
        dim3 grid(DIM / GBN, MROWS, NRELS);
        gemm_f16<<<grid, 256, SMEMB>>>(p_bh, p_wh + WREL_OFF, nullptr, p_yh, b_rel,
                                       NN, DIM, DIM, (long long)DIM*DIM,
                                       (long long)NN*DIM, DIM, 1);
    }
    // selfh = fp16(base @ W_self.T + b_self)
    {
        dim3 grid(DIM / GBN, MROWS, 1);
        gemm_f16<<<grid, 256, SMEMB>>>(p_bh, p_wh + WSELF_OFF, nullptr, p_selfh, b_self,
                                       NN, DIM, DIM, 0, 0, 0, 1);
    }
    // fused CSR gather + LN1
    gather_ln1_kernel<<<NN, 128>>>(n1_g, n1_b);

    // FFN1 (+bias+gelu fused, fp16 output)
    {
        dim3 grid(FFDIM / GBN, MROWS, 1);
        gemm_f16<<<grid, 256, SMEMB>>>(p_x1h, p_wh + WF1_OFF, nullptr, p_uh, bf1,
                                       NN, FFDIM, DIM, 0, 0, 0, 2);
    }
    // FFN2 -> g_agg fp32 (bf2 added in final_fuse)
    {
        dim3 grid(DIM / GBN, MROWS, 1);
        gemm_f16<<<grid, 256, SMEMB>>>(p_uh, p_wh + WF2_OFF, p_agg, nullptr, nullptr,
                                       NN, DIM, FFDIM, 0, 0, 0, 0);
    }

    final_fuse_kernel<<<NN, 256>>>(bf2, n2_g, n2_b, out_g, out_b, gml, out);
    pool_part_kernel<<<256, 512>>>(out);
    pool_final_kernel<<<1, 512>>>(out, dml, out + (long long)NN*DIM);
}

// round 17
// speedup vs baseline: 1.1765x; 1.0227x over previous
#include <cuda_runtime.h>
#include <cuda_fp16.h>
#include <math.h>
#include <stdint.h>

#define DIM 512
#define NN 50000
#define NE 100000
#define TOTE (2*NE)
#define NRELS 4
#define FFDIM 1024
#define NNP 50176              // 98*512 padded node count for scan
#define SCAN_NB 98

// ---------------- scratch (device globals; no allocation allowed) -------------
__device__ __half g_yh[NRELS*NN*DIM];    // per-rel transformed nodes (fp16)
__device__ float g_deg[NN];
__device__ float g_base[NN*DIM];
__device__ __half g_baseh[NN*DIM];
__device__ float g_agg[NN*DIM];          // FFN2 output
__device__ __half g_selfh[NN*DIM];       // base@Wself.T + b_self (fp16)
__device__ __half g_x1h[NN*DIM];
__device__ __half g_uh[NN*FFDIM];        // FFN hidden (post-gelu) fp16
#define NWELEM 2359296
#define WREL_OFF 0
#define WSELF_OFF 1048576
#define WF1_OFF 1310720
#define WF2_OFF 1835008
__device__ __half g_wh[NWELEM];
__device__ float g_part[256*DIM];
__device__ int   g_is64;
// CSR state
__device__ int   g_cnt[NNP];
__device__ int   g_cur[NNP];
__device__ int   g_off[NNP];
__device__ int   g_bsum[SCAN_NB];
__device__ int   g_boff[SCAN_NB+2];
__device__ int   g_epack[TOTE];          // src | (rel<<17)
__device__ float g_eww[TOTE];

// ---------------- index dtype detection --------------------------------------
__global__ void detect_idx_kernel(const unsigned int* __restrict__ w) {
    __shared__ int nz;
    if (threadIdx.x == 0) nz = 0;
    __syncthreads();
    int found = 0;
    for (int i = threadIdx.x; i < TOTE/2 * 2; i += blockDim.x) {
        if (w[2*i + 1] != 0u) { found = 1; break; }
        if (2*i + 1 >= TOTE - 1) break;
    }
    if (found) atomicOr(&nz, 1);
    __syncthreads();
    if (threadIdx.x == 0) g_is64 = nz ? 0 : 1;
}

__device__ __forceinline__ int ldidx(const void* p, long long i) {
    return g_is64 ? (int)((const long long*)p)[i] : ((const int*)p)[i];
}

// ---------------- edge decode --------------------------------------------------
__device__ __forceinline__ void edge_decode(const void* ei, const void* et,
                                            const float* ew, int e,
                                            int& src, int& dst, int& rel, float& w) {
    if (e < NE) {
        src = ldidx(ei, e); dst = ldidx(ei, NE + e);
        rel = ldidx(et, e); w = ew[e];
    } else {
        int e2 = e - NE;
        src = ldidx(ei, NE + e2); dst = ldidx(ei, e2);
        rel = ldidx(et, e2) + 2;  w = ew[e2];
    }
}

// ---------------- zero small state ---------------------------------------------
__global__ void zero_small_kernel() {        // 98 blocks x 512
    int j = blockIdx.x*512 + threadIdx.x;
    g_cnt[j] = 0; g_cur[j] = 0;
    if (j < NN) g_deg[j] = 0.f;
}

// ---------------- CSR: count / scan / fill -------------------------------------
__global__ void count_kernel(const void* __restrict__ ei, const void* __restrict__ et,
                             const float* __restrict__ ew) {
    int e = blockIdx.x * blockDim.x + threadIdx.x;
    if (e >= TOTE) return;
    int src, dst, rel; float w;
    edge_decode(ei, et, ew, e, src, dst, rel, w);
    atomicAdd(&g_cnt[dst], 1);
    atomicAdd(&g_deg[dst], w);
}

__global__ void scan_sum_kernel() {          // 98 blocks x 512
    __shared__ int sh[512];
    int b = blockIdx.x, t = threadIdx.x;
    sh[t] = g_cnt[b*512 + t];
    __syncthreads();
    for (int s = 256; s > 0; s >>= 1) {
        if (t < s) sh[t] += sh[t+s];
        __syncthreads();
    }
    if (t == 0) g_bsum[b] = sh[0];
}

__global__ void scan_off_kernel() {          // 1 block x 128
    __shared__ int sh[128];
    int t = threadIdx.x;
    sh[t] = (t < SCAN_NB) ? g_bsum[t] : 0;
    __syncthreads();
    for (int s = 1; s < 128; s <<= 1) {
        int v = (t >= s) ? sh[t-s] : 0;
        __syncthreads();
        sh[t] += v;
        __syncthreads();
    }
    if (t < SCAN_NB) g_boff[t+1] = sh[t];
    if (t == 0) g_boff[0] = 0;
}

__global__ void scan_write_kernel() {        // 98 blocks x 512
    __shared__ int sh[512];
    int b = blockIdx.x, t = threadIdx.x;
    int j = b*512 + t;
    int c = g_cnt[j];
    sh[t] = c;
    __syncthreads();
    for (int s = 1; s < 512; s <<= 1) {
        int v = (t >= s) ? sh[t-s] : 0;
        __syncthreads();
        sh[t] += v;
        __syncthreads();
    }
    g_off[j] = g_boff[b] + sh[t] - c;        // exclusive start
}

__global__ void fill_kernel(const void* __restrict__ ei, const void* __restrict__ et,
                            const float* __restrict__ ew) {
    int e = blockIdx.x * blockDim.x + threadIdx.x;
    if (e >= TOTE) return;
    int src, dst, rel; float w;
    edge_decode(ei, et, ew, e, src, dst, rel, w);
    int pos = g_off[dst] + atomicAdd(&g_cur[dst], 1);
    g_epack[pos] = src | (rel << 17);
    g_eww[pos] = w;
}

// ---------------- input LayerNorm ---------------------------------------------
__global__ void input_ln_kernel(const float* __restrict__ nf, const void* __restrict__ ntype,
                                const float* __restrict__ emb, const float* __restrict__ gw,
                                const float* __restrict__ gb) {
    __shared__ float2 red[256];
    int row = blockIdx.x, t = threadIdx.x;
    int nt = ldidx(ntype, row);
    long long off = (long long)row * DIM;
    float v0 = nf[off + t]       + emb[nt*DIM + t];
    float v1 = nf[off + t + 256] + emb[nt*DIM + t + 256];
    red[t] = make_float2(v0 + v1, v0*v0 + v1*v1);
    __syncthreads();
    for (int s = 128; s > 0; s >>= 1) {
        if (t < s) { red[t].x += red[t+s].x; red[t].y += red[t+s].y; }
        __syncthreads();
    }
    float m = red[0].x * (1.f/DIM);
    float var = red[0].y * (1.f/DIM) - m*m;
    float r = rsqrtf(var + 1e-5f);
    float b0 = (v0 - m)*r*gw[t]     + gb[t];
    float b1 = (v1 - m)*r*gw[t+256] + gb[t+256];
    g_base[off + t]       = b0;
    g_base[off + t + 256] = b1;
    g_baseh[off + t]       = __float2half(b0);
    g_baseh[off + t + 256] = __float2half(b1);
}

// ---------------- weight convert ----------------------------------------------
__global__ void conv_w_kernel(const float* __restrict__ src, int n, int off) {
    for (int i = blockIdx.x*blockDim.x + threadIdx.x; i < n; i += gridDim.x*blockDim.x)
        g_wh[off + i] = __float2half(src[i]);
}

// ================= fp16 tensor-core GEMM (NT, mma.sync) =======================
// 256 threads, 8 warps (warp tile 32x64), 4-stage cp.async pipeline,
// single __syncthreads per k-iteration.
#define GBM 128
#define GBN 128
#define GBK 32
#define STG 16384
#define NSTAGE 4

__device__ __forceinline__ void ldsm4(uint32_t* r, uint32_t addr) {
    asm volatile("ldmatrix.sync.aligned.m8n8.x4.shared.b16 {%0,%1,%2,%3},[%4];\n"
        : "=r"(r[0]), "=r"(r[1]), "=r"(r[2]), "=r"(r[3]) : "r"(addr));
}
__device__ __forceinline__ void mma_f16(float* d, const uint32_t* a, uint32_t b0, uint32_t b1) {
    asm volatile("mma.sync.aligned.m16n8k16.row.col.f32.f16.f16.f32 "
        "{%0,%1,%2,%3},{%4,%5,%6,%7},{%8,%9},{%0,%1,%2,%3};\n"
        : "+f"(d[0]), "+f"(d[1]), "+f"(d[2]), "+f"(d[3])
        : "r"(a[0]), "r"(a[1]), "r"(a[2]), "r"(a[3]), "r"(b0), "r"(b1));
}
__device__ __forceinline__ void cp16(uint32_t dst, const void* src, int sz) {
    asm volatile("cp.async.cg.shared.global [%0],[%1],16,%2;\n" :: "r"(dst), "l"(src), "r"(sz));
}

// mode: 0 = fp32 C = acc (+bias if bias)   1 = fp16 O = acc + bias
//       2 = fp16 O = gelu(acc + bias)
__global__ void __launch_bounds__(256) gemm_f16(
    const __half* __restrict__ A, const __half* __restrict__ B,
    float* __restrict__ C, __half* __restrict__ O, const float* __restrict__ bias,
    int M, int N, int K, long long bStrideZ, long long outStrideZ, long long biasStrideZ, int mode)
{
    extern __shared__ __align__(1024) char smraw[];
    const int tid = threadIdx.x;
    const int lane = tid & 31, wid = tid >> 5;
    const int wm = wid & 3, wn = wid >> 2;        // warp grid 4(M) x 2(N)
    const int bm = blockIdx.y * GBM, bn = blockIdx.x * GBN, z = blockIdx.z;
    const __half* Bz = B + (long long)z * bStrideZ;
    const int niter = K / GBK;
    uint32_t smbase = (uint32_t)__cvta_generic_to_shared(smraw);

    const int cc = tid & 3;          // 16B chunk within a 64B k-slice
    const int rr = tid >> 2;         // 0..63
    long long arow[2];
    int avalid[2];
    #pragma unroll
    for (int i = 0; i < 2; i++) {
        int gr = bm + i*64 + rr;
        bool ok = (gr < M);
        arow[i] = (long long)(ok ? gr : 0) * K;
        avalid[i] = ok ? 16 : 0;
    }

    float acc[2][8][4];
    #pragma unroll
    for (int i = 0; i < 2; i++)
        #pragma unroll
        for (int j = 0; j < 8; j++)
            #pragma unroll
            for (int c = 0; c < 4; c++) acc[i][j][c] = 0.f;

    auto issue_copy = [&](int stage, int it) {
        int kb = it * GBK;
        #pragma unroll
        for (int i = 0; i < 2; i++) {
            int row = i*64 + rr;
            uint32_t dst = smbase + stage*STG
                         + (uint32_t)(row*64 + ((cc ^ ((row>>1)&3)) << 4));
            cp16(dst, A + arow[i] + kb + cc*8, avalid[i]);
        }
        #pragma unroll
        for (int i = 0; i < 2; i++) {
            int row = i*64 + rr;
            uint32_t dst = smbase + stage*STG + 8192
                         + (uint32_t)(row*64 + ((cc ^ ((row>>1)&3)) << 4));
            cp16(dst, Bz + (long long)(bn + row)*K + kb + cc*8, 16);
        }
        asm volatile("cp.async.commit_group;\n" ::: "memory");
    };

    issue_copy(0, 0);
    if (niter > 1) issue_copy(1, 1);
    if (niter > 2) issue_copy(2, 2);

    int stage = 0;
    for (int it = 0; it < niter; ++it) {
        // Drain so that group `it` is complete: wait_n = min(2, niter-it-1)
        if (it + 3 <= niter) {
            asm volatile("cp.async.wait_group 2;\n" ::: "memory");
        } else if (it + 2 == niter) {
            asm volatile("cp.async.wait_group 1;\n" ::: "memory");
        } else {
            asm volatile("cp.async.wait_group 0;\n" ::: "memory");
        }
        __syncthreads();   // data visible to all; all warps done reading stage-1

        // overwrite the stage read in iteration it-1 (safe after the barrier)
        if (it + 3 < niter) {
            int s3 = stage + 3; if (s3 >= NSTAGE) s3 -= NSTAGE;
            issue_copy(s3, it + 3);
        }

        uint32_t sA = smbase + stage*STG;
        uint32_t sB = sA + 8192;
        int rsel = lane & 15;
        #pragma unroll
        for (int kk = 0; kk < 2; kk++) {
            int csel = kk*2 + (lane >> 4);
            uint32_t ah[2][4], bh[4][4];
            #pragma unroll
            for (int mi = 0; mi < 2; mi++) {
                int row = wm*32 + mi*16 + rsel;
                uint32_t off = (uint32_t)(row*64 + ((csel ^ ((row>>1)&3)) << 4));
                ldsm4(ah[mi], sA + off);
            }
            #pragma unroll
            for (int p = 0; p < 4; p++) {
                int row = wn*64 + p*16 + rsel;
                uint32_t off = (uint32_t)(row*64 + ((csel ^ ((row>>1)&3)) << 4));
                ldsm4(bh[p], sB + off);
            }
            #pragma unroll
            for (int mi = 0; mi < 2; mi++)
                #pragma unroll
                for (int nj = 0; nj < 8; nj++) {
                    int p = nj >> 1, h = nj & 1;
                    mma_f16(acc[mi][nj], ah[mi], bh[p][h], bh[p][2+h]);
                }
        }
        if (++stage == NSTAGE) stage = 0;
    }

    // ---- epilogue -----------------------------------------------------------
    #pragma unroll
    for (int mi = 0; mi < 2; mi++) {
        #pragma unroll
        for (int nj = 0; nj < 8; nj++) {
            int gc = bn + wn*64 + nj*8 + (lane & 3)*2;
            #pragma unroll
            for (int half = 0; half < 2; half++) {
                int gr = bm + wm*32 + mi*16 + (lane >> 2) + half*8;
                if (gr >= M) continue;
                float v0 = acc[mi][nj][half*2 + 0];
                float v1 = acc[mi][nj][half*2 + 1];
                if (mode == 0) {
                    if (bias) {
                        const float* bs = bias + (long long)z*biasStrideZ;
                        v0 += bs[gc]; v1 += bs[gc+1];
                    }
                    float* Cp = C + (long long)z*outStrideZ + (long long)gr*N + gc;
                    float2 w2 = make_float2(v0, v1);
                    *(float2*)Cp = w2;
                } else {
                    const float* bs = bias + (long long)z*biasStrideZ;
                    v0 += bs[gc]; v1 += bs[gc+1];
                    if (mode == 2) {
                        v0 = 0.5f * v0 * (1.f + erff(v0 * 0.70710678118654752f));
                        v1 = 0.5f * v1 * (1.f + erff(v1 * 0.70710678118654752f));
                    }
                    __half2 o;
                    o.x = __float2half(v0);
                    o.y = __float2half(v1);
                    *(__half2*)(O + (long long)z*outStrideZ + (long long)gr*N + gc) = o;
                }
            }
        }
    }
}

// ---------------- fused CSR gather + LN1 ---------------------------------------
__global__ void __launch_bounds__(128) gather_ln1_kernel(
    const float* __restrict__ gw, const float* __restrict__ gb) {
    __shared__ float2 red[128];
    int n = blockIdx.x, t = threadIdx.x;
    int off = g_off[n], cnt = g_cnt[n];
    float a0 = 0.f, a1 = 0.f, a2 = 0.f, a3 = 0.f;
    for (int j = off; j < off + cnt; j++) {
        int pk = g_epack[j];
        float w = g_eww[j];
        int src = pk & 0x1FFFF, rel = pk >> 17;
        uint2 p = *(const uint2*)(g_yh + ((long long)rel*NN + src)*DIM + t*4);
        __half2 h0 = *(__half2*)&p.x, h1 = *(__half2*)&p.y;
        a0 += w * __half2float(h0.x);
        a1 += w * __half2float(h0.y);
        a2 += w * __half2float(h1.x);
        a3 += w * __half2float(h1.y);
    }
    float inv = 1.f / fmaxf(g_deg[n], 1.f);
    long long o = (long long)n * DIM + t*4;
    float4 bs = *(const float4*)(g_base + o);
    uint2 sp = *(const uint2*)(g_selfh + o);
    __half2 s0 = *(__half2*)&sp.x, s1 = *(__half2*)&sp.y;
    float v0 = bs.x + a0*inv + __half2float(s0.x);
    float v1 = bs.y + a1*inv + __half2float(s0.y);
    float v2 = bs.z + a2*inv + __half2float(s1.x);
    float v3 = bs.w + a3*inv + __half2float(s1.y);
    red[t] = make_float2(v0+v1+v2+v3, v0*v0+v1*v1+v2*v2+v3*v3);
    __syncthreads();
    for (int s = 64; s > 0; s >>= 1) {
        if (t < s) { red[t].x += red[t+s].x; red[t].y += red[t+s].y; }
        __syncthreads();
    }
    float m = red[0].x * (1.f/DIM);
    float var = red[0].y * (1.f/DIM) - m*m;
    float r = rsqrtf(var + 1e-5f);
    int c = t*4;
    __half2 o0, o1;
    o0.x = __float2half((v0 - m)*r*gw[c]   + gb[c]);
    o0.y = __float2half((v1 - m)*r*gw[c+1] + gb[c+1]);
    o1.x = __float2half((v2 - m)*r*gw[c+2] + gb[c+2]);
    o1.y = __float2half((v3 - m)*r*gw[c+3] + gb[c+3]);
    uint2 outp;
    *(__half2*)&outp.x = o0;
    *(__half2*)&outp.y = o1;
    *(uint2*)(g_x1h + o) = outp;
}

// ---------------- final fused: LN2 -> out-LN -> graph mix ---------------------
__global__ void final_fuse_kernel(const float* __restrict__ bf2,
                                  const float* __restrict__ n2g, const float* __restrict__ n2b,
                                  const float* __restrict__ og,  const float* __restrict__ ob,
                                  const float* __restrict__ gml, float* __restrict__ out) {
    __shared__ float2 red[256];
    int row = blockIdx.x, t = threadIdx.x;
    long long off = (long long)row * DIM;
    float t0 = __half2float(g_x1h[off+t])     + g_agg[off+t]     + bf2[t];
    float t1 = __half2float(g_x1h[off+t+256]) + g_agg[off+t+256] + bf2[t+256];
    red[t] = make_float2(t0 + t1, t0*t0 + t1*t1);
    __syncthreads();
    for (int s = 128; s > 0; s >>= 1) {
        if (t < s) { red[t].x += red[t+s].x; red[t].y += red[t+s].y; }
        __syncthreads();
    }
    float m = red[0].x * (1.f/DIM);
    float var = red[0].y * (1.f/DIM) - m*m;
    float r = rsqrtf(var + 1e-5f);
    float x20 = (t0 - m)*r*n2g[t]     + n2b[t];
    float x21 = (t1 - m)*r*n2g[t+256] + n2b[t+256];
    __syncthreads();
    red[t] = make_float2(x20 + x21, x20*x20 + x21*x21);
    __syncthreads();
    for (int s = 128; s > 0; s >>= 1) {
        if (t < s) { red[t].x += red[t+s].x; red[t].y += red[t+s].y; }
        __syncthreads();
    }
    m = red[0].x * (1.f/DIM);
    var = red[0].y * (1.f/DIM) - m*m;
    r = rsqrtf(var + 1e-5f);
    float x30 = (x20 - m)*r*og[t]     + ob[t];
    float x31 = (x21 - m)*r*og[t+256] + ob[t+256];
    float gm = 1.f / (1.f + expf(-gml[0]));
    float b0 = g_base[off+t], b1 = g_base[off+t+256];
    out[off+t]     = b0 + gm*(x30 - b0);
    out[off+t+256] = b1 + gm*(x31 - b1);
}

// ---------------- pooling -----------------------------------------------------
__global__ void pool_part_kernel(const float* __restrict__ x) {
    int b = blockIdx.x;
    int t = threadIdx.x;
    float s = 0.f;
    for (int r = b; r < NN; r += 256)
        s += x[(long long)r*DIM + t];
    g_part[b*DIM + t] = s;
}

__global__ void pool_final_kernel(const float* __restrict__ x, const float* __restrict__ dml,
                                  float* __restrict__ pooled) {
    int t = threadIdx.x;
    float s = 0.f;
    for (int b = 0; b < 256; ++b) s += g_part[b*DIM + t];
    float mean = s * (1.f / NN);
    float dm = 1.f / (1.f + expf(-dml[0]));
    pooled[t] = dm * x[t] + (1.f - dm) * mean;
}

// ---------------- host launcher ----------------------------------------------
extern "C" void kernel_launch(void* const* d_in, const int* in_sizes, int n_in,
                              void* d_out, int out_size) {
    (void)in_sizes; (void)n_in; (void)out_size;
    const float* nf     = (const float*)d_in[0];
    const void*  ei     = d_in[1];
    const void*  et     = d_in[2];
    const void*  ntype  = d_in[3];
    const float* ew     = (const float*)d_in[4];
    const float* emb    = (const float*)d_in[5];
    const float* W_self = (const float*)d_in[6];
    const float* b_self = (const float*)d_in[7];
    const float* W_rel  = (const float*)d_in[8];
    const float* b_rel  = (const float*)d_in[9];
    const float* in_g   = (const float*)d_in[10];
    const float* in_b   = (const float*)d_in[11];
    const float* n1_g   = (const float*)d_in[12];
    const float* n1_b   = (const float*)d_in[13];
    const float* Wf1    = (const float*)d_in[14];
    const float* bf1    = (const float*)d_in[15];
    const float* Wf2    = (const float*)d_in[16];
    const float* bf2    = (const float*)d_in[17];
    const float* n2_g   = (const float*)d_in[18];
    const float* n2_b   = (const float*)d_in[19];
    const float* out_g  = (const float*)d_in[20];
    const float* out_b  = (const float*)d_in[21];
    const float* gml    = (const float*)d_in[22];
    const float* dml    = (const float*)d_in[23];
    float* out = (float*)d_out;

    static bool init = false;
    static float *p_agg;
    static __half *p_yh, *p_bh, *p_selfh, *p_x1h, *p_uh, *p_wh;
    if (!init) {
        cudaGetSymbolAddress((void**)&p_yh,    g_yh);
        cudaGetSymbolAddress((void**)&p_agg,   g_agg);
        cudaGetSymbolAddress((void**)&p_selfh, g_selfh);
        cudaGetSymbolAddress((void**)&p_bh,    g_baseh);
        cudaGetSymbolAddress((void**)&p_x1h,   g_x1h);
        cudaGetSymbolAddress((void**)&p_uh,    g_uh);
        cudaGetSymbolAddress((void**)&p_wh,    g_wh);
        cudaFuncSetAttribute(gemm_f16, cudaFuncAttributeMaxDynamicSharedMemorySize,
                             NSTAGE*STG);
        init = true;
    }

    const int MROWS = (NN + GBM - 1) / GBM;   // 391
    const int SMEMB = NSTAGE*STG;             // 65536 (64KB)

    detect_idx_kernel<<<1, 256>>>((const unsigned int*)ei);
    zero_small_kernel<<<SCAN_NB, 512>>>();
    input_ln_kernel<<<NN, 256>>>(nf, ntype, emb, in_g, in_b);
    conv_w_kernel<<<2048, 256>>>(W_rel,  NRELS*DIM*DIM, WREL_OFF);
    conv_w_kernel<<<512,  256>>>(W_self, DIM*DIM,       WSELF_OFF);
    conv_w_kernel<<<1024, 256>>>(Wf1,    FFDIM*DIM,     WF1_OFF);
    conv_w_kernel<<<1024, 256>>>(Wf2,    DIM*FFDIM,     WF2_OFF);

    // CSR build
    count_kernel<<<(TOTE + 255)/256, 256>>>(ei, et, ew);
    scan_sum_kernel<<<SCAN_NB, 512>>>();
    scan_off_kernel<<<1, 128>>>();
    scan_write_kernel<<<SCAN_NB, 512>>>();
    fill_kernel<<<(TOTE + 255)/256, 256>>>(ei, et, ew);

    // y[rel] = fp16(base @ W_rel[rel].T + b_rel[rel])
    {
        dim3 grid(DIM / GBN, MROWS, NRELS);
        gemm_f16<<<grid, 256, SMEMB>>>(p_bh, p_wh + WREL_OFF, nullptr, p_yh, b_rel,
                                       NN, DIM, DIM, (long long)DIM*DIM,
                                       (long long)NN*DIM, DIM, 1);
    }
    // selfh = fp16(base @ W_self.T + b_self)
    {
        dim3 grid(DIM / GBN, MROWS, 1);
        gemm_f16<<<grid, 256, SMEMB>>>(p_bh, p_wh + WSELF_OFF, nullptr, p_selfh, b_self,
                                       NN, DIM, DIM, 0, 0, 0, 1);
    }
    // fused CSR gather + LN1
    gather_ln1_kernel<<<NN, 128>>>(n1_g, n1_b);

    // FFN1 (+bias+gelu fused, fp16 output)
    {
        dim3 grid(FFDIM / GBN, MROWS, 1);
        gemm_f16<<<grid, 256, SMEMB>>>(p_x1h, p_wh + WF1_OFF, nullptr, p_uh, bf1,
                                       NN, FFDIM, DIM, 0, 0, 0, 2);
    }
    // FFN2 -> g_agg fp32 (bf2 added in final_fuse)
    {
        dim3 grid(DIM / GBN, MROWS, 1);
        gemm_f16<<<grid, 256, SMEMB>>>(p_uh, p_wh + WF2_OFF, p_agg, nullptr, nullptr,
                                       NN, DIM, FFDIM, 0, 0, 0, 0);
    }

    final_fuse_kernel<<<NN, 256>>>(bf2, n2_g, n2_b, out_g, out_b, gml, out);
    pool_part_kernel<<<256, 512>>>(out);
    pool_final_kernel<<<1, 512>>>(out, dml, out + (long long)NN*DIM);
}